// round 10
// baseline (speedup 1.0000x reference)
#include <cuda_runtime.h>
#include <math.h>

// Batched FFT: B=8192 rows, N=4096, complex fp32 (separate re/im), out = [Yre; Yim].
//
// Radix-16^3 four-step, packed f32x2 arithmetic (round-8 proven structure),
// now TWO rows per CTA in the same threads: twiddle bases + recurrence advances
// + barriers amortized over both rows, 2x ILP / MLP per warp.
//
//   n = n1*256 + n2, k = k2*16 + k1, n2 = p1*16 + p2, k2 = q2*16 + q1.
// Pass 1 (t=n2):   A[k1] = DFT16_{n1}(x[n1*256+t]) * W4096^{t*k1}
// Exch 1 (pad 257, per-row buffer)
// Pass 2 (k1,p2):  C[q1] = DFT16_{p1}(...) * W256^{p2*q1}
// Exch 2 ([q1*256+t], same buffers)
// Pass 3 (k1,q1):  Y[q2*256 + t] = DFT16_{p2}(...)

#define NFFT 4096
#define TPB  256
#define EXSZ (16 * 257)                       // per-row exchange buffer (c64)
#define SMEM_BYTES (2 * EXSZ * 8)             // 65792 B dynamic

typedef unsigned long long c64;   // packed complex: lo 32 = re, hi 32 = im

__device__ __forceinline__ c64 cpack(float re, float im) {
    c64 r;
    asm("mov.b64 %0, {%1, %2};" : "=l"(r) : "f"(re), "f"(im));
    return r;
}
__device__ __forceinline__ void cunpack(c64 v, float& re, float& im) {
    asm("mov.b64 {%0, %1}, %2;" : "=f"(re), "=f"(im) : "l"(v));
}
__device__ __forceinline__ c64 padd(c64 a, c64 b) {
    c64 r;
    asm("add.rn.f32x2 %0, %1, %2;" : "=l"(r) : "l"(a), "l"(b));
    return r;
}
__device__ __forceinline__ c64 pmul(c64 a, c64 b) {
    c64 r;
    asm("mul.rn.f32x2 %0, %1, %2;" : "=l"(r) : "l"(a), "l"(b));
    return r;
}
__device__ __forceinline__ c64 pfma(c64 a, c64 b, c64 c) {
    c64 r;
    asm("fma.rn.f32x2 %0, %1, %2, %3;" : "=l"(r) : "l"(a), "l"(b), "l"(c));
    return r;
}
__device__ __forceinline__ c64 pswap(c64 a) {   // (re,im) -> (im,re)
    c64 r;
    asm("{\n\t.reg .b32 lo, hi;\n\tmov.b64 {lo, hi}, %1;\n\tmov.b64 %0, {hi, lo};\n\t}"
        : "=l"(r) : "l"(a));
    return r;
}

#define K_NEG1 cpack(-1.0f, -1.0f)
#define K_PM   cpack( 1.0f, -1.0f)
#define K_MP   cpack(-1.0f,  1.0f)

__device__ __forceinline__ c64 psub(c64 a, c64 b) { return pfma(b, K_NEG1, a); }
// complex mul by twiddle held split: xx=(bx,bx), nyy=(-by,by)
__device__ __forceinline__ c64 cmul_t(c64 a, c64 xx, c64 nyy) {
    return pfma(a, xx, pmul(pswap(a), nyy));
}
__device__ __forceinline__ c64 cnegi(c64 a) { return pmul(pswap(a), K_PM); }

// forward DFT4 (W4 = -i), packed: 9 f32x2 ops
__device__ __forceinline__ void dft4(c64 a, c64 b, c64 c, c64 d,
                                     c64& o0, c64& o1, c64& o2, c64& o3) {
    c64 s0 = padd(a, c);
    c64 s1 = psub(a, c);
    c64 s2 = padd(b, d);
    c64 s3 = psub(b, d);
    o0 = padd(s0, s2);
    o2 = psub(s0, s2);
    c64 s3r = pswap(s3);
    o1 = pfma(s3r, K_PM, s1);   // s1 - i*s3
    o3 = pfma(s3r, K_MP, s1);   // s1 + i*s3
}

// 16-point forward DFT, natural in -> natural out (radix-4 x radix-4), packed.
__device__ __forceinline__ void fft16(c64 v[16]) {
    const float C1 = 0.92387953251128675613f;  // cos(pi/8)
    const float S1 = 0.38268343236508977173f;  // sin(pi/8)
    const float R  = 0.70710678118654752440f;  // sqrt(2)/2

    c64 a[4][4];
#pragma unroll
    for (int l = 0; l < 4; l++)
        dft4(v[l], v[l + 4], v[l + 8], v[l + 12],
             a[l][0], a[l][1], a[l][2], a[l][3]);

    a[1][1] = cmul_t(a[1][1], cpack( C1,  C1), cpack( S1, -S1));
    a[1][2] = cmul_t(a[1][2], cpack(  R,   R), cpack(  R,  -R));
    a[1][3] = cmul_t(a[1][3], cpack( S1,  S1), cpack( C1, -C1));
    a[2][1] = cmul_t(a[2][1], cpack(  R,   R), cpack(  R,  -R));
    a[2][2] = cnegi(a[2][2]);
    a[2][3] = cmul_t(a[2][3], cpack( -R,  -R), cpack(  R,  -R));
    a[3][1] = cmul_t(a[3][1], cpack( S1,  S1), cpack( C1, -C1));
    a[3][2] = cmul_t(a[3][2], cpack( -R,  -R), cpack(  R,  -R));
    a[3][3] = cmul_t(a[3][3], cpack(-C1, -C1), cpack(-S1,  S1));

#pragma unroll
    for (int p = 0; p < 4; p++)
        dft4(a[0][p], a[1][p], a[2][p], a[3][p],
             v[p], v[4 + p], v[8 + p], v[12 + p]);
}

// vA[k] *= w^k and vB[k] *= w^k, k=1..15 — ONE recurrence serves both rows.
// w^8 via 3 scalar squarings; two split-form chains (k=1..7, 8..15) in parallel.
__device__ __forceinline__ void twiddle16_pair(c64 vA[16], c64 vB[16],
                                               float c, float s) {
    float c2 = fmaf(c,  c,  -s  * s ),  s2 = 2.0f * c  * s;
    float c4 = fmaf(c2, c2, -s2 * s2),  s4 = 2.0f * c2 * s2;
    float c8 = fmaf(c4, c4, -s4 * s4),  s8 = 2.0f * c4 * s4;

    const c64 cwxx = cpack( c,  c);
    const c64 wsnn = cpack(-s,  s);
    const c64 wsnp = cpack( s, -s);

    c64 caxx = cwxx;                  // A-chain = w^1
    c64 sann = wsnn;
    c64 cbxx = cpack( c8, c8);        // B-chain = w^8
    c64 sbnn = cpack(-s8, s8);

    vA[8] = cmul_t(vA[8], cbxx, sbnn);
    vB[8] = cmul_t(vB[8], cbxx, sbnn);
#pragma unroll
    for (int k = 1; k < 8; k++) {
        vA[k] = cmul_t(vA[k], caxx, sann);
        vB[k] = cmul_t(vB[k], caxx, sann);
        c64 ncb = pfma(cbxx, cwxx, pmul(sbnn, wsnp));
        c64 nsb = pfma(sbnn, cwxx, pmul(cbxx, wsnn));
        cbxx = ncb; sbnn = nsb;
        vA[8 + k] = cmul_t(vA[8 + k], cbxx, sbnn);
        vB[8 + k] = cmul_t(vB[8 + k], cbxx, sbnn);
        if (k < 7) {
            c64 nca = pfma(caxx, cwxx, pmul(sann, wsnp));
            c64 nsa = pfma(sann, cwxx, pmul(caxx, wsnn));
            caxx = nca; sann = nsa;
        }
    }
}

__global__ void __launch_bounds__(TPB, 2)
fft4096_x2(const float* __restrict__ xre,
           const float* __restrict__ xim,
           float* __restrict__ out,
           int batch) {
    extern __shared__ __align__(16) c64 sh[];
    c64* shA = sh;
    c64* shB = sh + EXSZ;

    const int t  = threadIdx.x;
    const int k1 = t & 15;
    const int hi = t >> 4;   // p2 in pass 2, q1 in pass 3
    const int r0 = blockIdx.x * 2;
    const int r1 = r0 + 1;

    // one pair of twiddle bases serves both rows (depend only on t)
    float s1, c1, s2, c2;
    sincosf((float)t  * (-6.2831853071795864769f / 4096.0f), &s1, &c1);
    sincosf((float)hi * (-6.2831853071795864769f /  256.0f), &s2, &c2);

    const float* xr0 = xre + (size_t)r0 * NFFT;
    const float* xi0 = xim + (size_t)r0 * NFFT;
    const float* xr1 = xre + (size_t)r1 * NFFT;
    const float* xi1 = xim + (size_t)r1 * NFFT;

    c64 vA[16], vB[16];
#pragma unroll
    for (int n1 = 0; n1 < 16; n1++) {
        vA[n1] = cpack(__ldcs(&xr0[n1 * 256 + t]), __ldcs(&xi0[n1 * 256 + t]));
        vB[n1] = cpack(__ldcs(&xr1[n1 * 256 + t]), __ldcs(&xi1[n1 * 256 + t]));
    }

    // ---- pass 1: DFT16 over n1 (thread t = n2), twiddle W4096^{t*k1} ----
    fft16(vA);
    fft16(vB);
    twiddle16_pair(vA, vB, c1, s1);

    // ---- exchange 1: sh[k1*257 + n2] ----
#pragma unroll
    for (int k = 0; k < 16; k++) {
        shA[k * 257 + t] = vA[k];
        shB[k * 257 + t] = vB[k];
    }
    __syncthreads();
#pragma unroll
    for (int p1 = 0; p1 < 16; p1++) {
        vA[p1] = shA[k1 * 257 + p1 * 16 + hi];
        vB[p1] = shB[k1 * 257 + p1 * 16 + hi];
    }

    // ---- pass 2: DFT16 over p1 -> q1, twiddle W256^{p2*q1} ----
    fft16(vA);
    fft16(vB);
    twiddle16_pair(vA, vB, c2, s2);

    __syncthreads();

    // ---- exchange 2: sh[q1*256 + t] ----
#pragma unroll
    for (int q1 = 0; q1 < 16; q1++) {
        shA[q1 * 256 + t] = vA[q1];
        shB[q1 * 256 + t] = vB[q1];
    }
    __syncthreads();
#pragma unroll
    for (int p2 = 0; p2 < 16; p2++) {
        vA[p2] = shA[hi * 256 + p2 * 16 + k1];
        vB[p2] = shB[hi * 256 + p2 * 16 + k1];
    }

    // ---- pass 3: DFT16 over p2 -> q2;  Y[q2*256 + t] ----
    fft16(vA);
    fft16(vB);

    float* outreA = out + (size_t)r0 * NFFT;
    float* outimA = out + (size_t)batch * NFFT + (size_t)r0 * NFFT;
    float* outreB = out + (size_t)r1 * NFFT;
    float* outimB = out + (size_t)batch * NFFT + (size_t)r1 * NFFT;
#pragma unroll
    for (int q2 = 0; q2 < 16; q2++) {
        float re, im;
        cunpack(vA[q2], re, im);
        __stcs(&outreA[q2 * 256 + t], re);
        __stcs(&outimA[q2 * 256 + t], im);
        cunpack(vB[q2], re, im);
        __stcs(&outreB[q2 * 256 + t], re);
        __stcs(&outimB[q2 * 256 + t], im);
    }
}

extern "C" void kernel_launch(void* const* d_in, const int* in_sizes, int n_in,
                              void* d_out, int out_size) {
    const float* xre = (const float*)d_in[0];
    const float* xim = (const float*)d_in[1];
    float* out = (float*)d_out;
    const int batch = in_sizes[0] / NFFT;

    cudaFuncSetAttribute(fft4096_x2,
                         cudaFuncAttributeMaxDynamicSharedMemorySize, SMEM_BYTES);
    fft4096_x2<<<batch / 2, TPB, SMEM_BYTES>>>(xre, xim, out, batch);
}

// round 11
// speedup vs baseline: 1.1009x; 1.1009x over previous
#include <cuda_runtime.h>
#include <math.h>
#include <stdint.h>

// Batched FFT: B=8192 rows, N=4096, complex fp32 (separate re/im), out = [Yre; Yim].
//
// Radix-16^3 four-step, packed f32x2 arithmetic (round-8 skeleton: one row/CTA,
// 3 barriers, 4 CTAs/SM). This round removes BOTH twiddle recurrences:
//  - compile-time constexpr twiddle tables in __device__ memory (no init kernel)
//  - tw1 laid out [k*257+t] == exchange-1 addressing; each thread cp.asyncs its
//    OWN 15 entries into slots only it reads and later overwrites -> no barrier
//  - tw2 (2KB) cooperative cp.async; visibility via the existing exch-1 barrier
//  - apply = LDS + split-on-the-fly complex mul (sign flip on ALU pipe)
//
//   n = n1*256 + n2, k = k2*16 + k1, n2 = p1*16 + p2, k2 = q2*16 + q1.
// Pass 1 (t=n2):   A[k1] = DFT16_{n1}(x[n1*256+t]) * W4096^{t*k1}
// Exch 1 (pad 257)
// Pass 2 (k1,p2):  C[q1] = DFT16_{p1}(...) * W256^{p2*q1}
// Exch 2 ([q1*256+t])
// Pass 3 (k1,q1):  Y[q2*256 + t] = DFT16_{p2}(...)

#define NFFT 4096
#define TPB  256

typedef unsigned long long c64;   // packed complex: lo 32 = re, hi 32 = im

// ---------------- compile-time twiddle tables ----------------

constexpr double CPI = 3.14159265358979323846264338327950288;

constexpr double tpoly_sin(double y) {
    double y2 = y * y, t = y, s = y;
    for (int n = 1; n <= 11; n++) { t *= -y2 / double((2 * n) * (2 * n + 1)); s += t; }
    return s;
}
constexpr double tpoly_cos(double y) {
    double y2 = y * y, t = 1.0, s = 1.0;
    for (int n = 1; n <= 11; n++) { t *= -y2 / double((2 * n - 1) * (2 * n)); s += t; }
    return s;
}
struct SCp { double s, c; };
constexpr SCp csc(double x) {   // |x| < 2*pi
    double r = x / (CPI / 2.0);
    int k = (int)(r >= 0.0 ? r + 0.5 : r - 0.5);
    double y = x - (double)k * (CPI / 2.0);
    double sy = tpoly_sin(y), cy = tpoly_cos(y);
    int m = ((k % 4) + 4) % 4;
    SCp o{0.0, 0.0};
    if (m == 0)      { o.s = sy;  o.c = cy;  }
    else if (m == 1) { o.s = cy;  o.c = -sy; }
    else if (m == 2) { o.s = -sy; o.c = -cy; }
    else             { o.s = -cy; o.c = sy;  }
    return o;
}

struct TwTab {
    float2 g1[16 * 257];   // g1[k*257 + t] = W4096^{t*k}  (row 0 / t=256 pad unused)
    float2 g2[256];        // g2[p*16 + q]  = W256^{p*q}
};
constexpr TwTab make_tw() {
    TwTab T{};
    for (int k = 0; k < 16; k++)
        for (int t = 0; t < 257; t++) {
            int tt = (t < 256) ? t : 0;
            SCp sc = csc(-2.0 * CPI * double(k * tt) / 4096.0);
            T.g1[k * 257 + t] = float2{(float)sc.c, (float)sc.s};
        }
    for (int p = 0; p < 16; p++)
        for (int q = 0; q < 16; q++) {
            SCp sc = csc(-2.0 * CPI * double(p * q) / 256.0);
            T.g2[p * 16 + q] = float2{(float)sc.c, (float)sc.s};
        }
    return T;
}
__device__ const TwTab g_tw = make_tw();

// ---------------- packed f32x2 primitives ----------------

__device__ __forceinline__ c64 cpack(float re, float im) {
    c64 r;
    asm("mov.b64 %0, {%1, %2};" : "=l"(r) : "f"(re), "f"(im));
    return r;
}
__device__ __forceinline__ void cunpack(c64 v, float& re, float& im) {
    asm("mov.b64 {%0, %1}, %2;" : "=f"(re), "=f"(im) : "l"(v));
}
__device__ __forceinline__ c64 padd(c64 a, c64 b) {
    c64 r;
    asm("add.rn.f32x2 %0, %1, %2;" : "=l"(r) : "l"(a), "l"(b));
    return r;
}
__device__ __forceinline__ c64 pmul(c64 a, c64 b) {
    c64 r;
    asm("mul.rn.f32x2 %0, %1, %2;" : "=l"(r) : "l"(a), "l"(b));
    return r;
}
__device__ __forceinline__ c64 pfma(c64 a, c64 b, c64 c) {
    c64 r;
    asm("fma.rn.f32x2 %0, %1, %2, %3;" : "=l"(r) : "l"(a), "l"(b), "l"(c));
    return r;
}
__device__ __forceinline__ c64 pswap(c64 a) {   // (re,im) -> (im,re)
    c64 r;
    asm("{\n\t.reg .b32 lo, hi;\n\tmov.b64 {lo, hi}, %1;\n\tmov.b64 %0, {hi, lo};\n\t}"
        : "=l"(r) : "l"(a));
    return r;
}

#define K_NEG1 cpack(-1.0f, -1.0f)
#define K_PM   cpack( 1.0f, -1.0f)
#define K_MP   cpack(-1.0f,  1.0f)

__device__ __forceinline__ c64 psub(c64 a, c64 b) { return pfma(b, K_NEG1, a); }
// complex mul by twiddle in split form: xx=(c,c), nyy=(-s,s)
__device__ __forceinline__ c64 cmul_t(c64 a, c64 xx, c64 nyy) {
    return pfma(a, xx, pmul(pswap(a), nyy));
}
// multiply by -i on the ALU pipe: (x,y) -> (y,-x)
__device__ __forceinline__ c64 cnegi(c64 a) {
    float x, y;
    cunpack(a, x, y);
    float nx = __uint_as_float(__float_as_uint(x) ^ 0x80000000u);
    return cpack(y, nx);
}
// complex mul by packed twiddle w=(c,s): split on the fly (sign flip on ALU)
__device__ __forceinline__ c64 cmul_w(c64 a, c64 w) {
    float wc, ws;
    cunpack(w, wc, ws);
    float nws = __uint_as_float(__float_as_uint(ws) ^ 0x80000000u);
    return pfma(a, cpack(wc, wc), pmul(pswap(a), cpack(nws, ws)));
}

__device__ __forceinline__ void cp_async8(unsigned dst, const void* src) {
    asm volatile("cp.async.ca.shared.global [%0], [%1], 8;"
                 :: "r"(dst), "l"(src) : "memory");
}
__device__ __forceinline__ void cp_async16(unsigned dst, const void* src) {
    asm volatile("cp.async.ca.shared.global [%0], [%1], 16;"
                 :: "r"(dst), "l"(src) : "memory");
}

// forward DFT4 (W4 = -i), packed
__device__ __forceinline__ void dft4(c64 a, c64 b, c64 c, c64 d,
                                     c64& o0, c64& o1, c64& o2, c64& o3) {
    c64 s0 = padd(a, c);
    c64 s1 = psub(a, c);
    c64 s2 = padd(b, d);
    c64 s3 = psub(b, d);
    o0 = padd(s0, s2);
    o2 = psub(s0, s2);
    c64 s3r = pswap(s3);
    o1 = pfma(s3r, K_PM, s1);   // s1 - i*s3
    o3 = pfma(s3r, K_MP, s1);   // s1 + i*s3
}

// 16-point forward DFT, natural in -> natural out (radix-4 x radix-4), packed.
__device__ __forceinline__ void fft16(c64 v[16]) {
    const float C1 = 0.92387953251128675613f;  // cos(pi/8)
    const float S1 = 0.38268343236508977173f;  // sin(pi/8)
    const float R  = 0.70710678118654752440f;  // sqrt(2)/2

    c64 a[4][4];
#pragma unroll
    for (int l = 0; l < 4; l++)
        dft4(v[l], v[l + 4], v[l + 8], v[l + 12],
             a[l][0], a[l][1], a[l][2], a[l][3]);

    a[1][1] = cmul_t(a[1][1], cpack( C1,  C1), cpack( S1, -S1));
    a[1][2] = cmul_t(a[1][2], cpack(  R,   R), cpack(  R,  -R));
    a[1][3] = cmul_t(a[1][3], cpack( S1,  S1), cpack( C1, -C1));
    a[2][1] = cmul_t(a[2][1], cpack(  R,   R), cpack(  R,  -R));
    a[2][2] = cnegi(a[2][2]);
    a[2][3] = cmul_t(a[2][3], cpack( -R,  -R), cpack(  R,  -R));
    a[3][1] = cmul_t(a[3][1], cpack( S1,  S1), cpack( C1, -C1));
    a[3][2] = cmul_t(a[3][2], cpack( -R,  -R), cpack(  R,  -R));
    a[3][3] = cmul_t(a[3][3], cpack(-C1, -C1), cpack(-S1,  S1));

#pragma unroll
    for (int p = 0; p < 4; p++)
        dft4(a[0][p], a[1][p], a[2][p], a[3][p],
             v[p], v[4 + p], v[8 + p], v[12 + p]);
}

__global__ void __launch_bounds__(TPB, 4)
fft4096_kernel(const float* __restrict__ xre,
               const float* __restrict__ xim,
               float* __restrict__ out,
               int batch) {
    __shared__ __align__(16) c64 sh[16 * 257];   // exchange buffer / tw1 cache
    __shared__ __align__(16) c64 tw2s[256];      // tw2 table (2 KB)

    const int b  = blockIdx.x;
    const int t  = threadIdx.x;
    const int k1 = t & 15;
    const int hi = t >> 4;   // p2 in pass 2, q1 in pass 3

    const float* xr = xre + (size_t)b * NFFT;
    const float* xi = xim + (size_t)b * NFFT;

    // global input loads first (highest priority for the DRAM stream)
    c64 v[16];
#pragma unroll
    for (int n1 = 0; n1 < 16; n1++)
        v[n1] = cpack(__ldcs(&xr[n1 * 256 + t]), __ldcs(&xi[n1 * 256 + t]));

    // async twiddle prefetch (L2-resident; lands during pass-1 compute)
    {
        unsigned shb  = (unsigned)__cvta_generic_to_shared(sh);
        unsigned tw2b = (unsigned)__cvta_generic_to_shared(tw2s);
#pragma unroll
        for (int k = 1; k < 16; k++)
            cp_async8(shb + (unsigned)((k * 257 + t) * 8), &g_tw.g1[k * 257 + t]);
        if (t < 128)
            cp_async16(tw2b + (unsigned)(t * 16),
                       (const char*)g_tw.g2 + t * 16);
        asm volatile("cp.async.commit_group;" ::: "memory");
    }

    // ---- pass 1: DFT16 over n1 (thread t = n2) ----
    fft16(v);

    asm volatile("cp.async.wait_group 0;" ::: "memory");

    // tw1 apply: thread t reads ONLY its own prefetched slots sh[k*257+t]
#pragma unroll
    for (int k = 1; k < 16; k++)
        v[k] = cmul_w(v[k], sh[k * 257 + t]);

    // ---- exchange 1: sh[k*257 + t] (overwrites own tw1 slots; same-thread WAR) ----
#pragma unroll
    for (int k = 0; k < 16; k++)
        sh[k * 257 + t] = v[k];
    __syncthreads();
#pragma unroll
    for (int p1 = 0; p1 < 16; p1++)
        v[p1] = sh[k1 * 257 + p1 * 16 + hi];

    // ---- pass 2: DFT16 over p1 -> q1, twiddle W256^{p2*q1} from smem table ----
    fft16(v);
#pragma unroll
    for (int q = 1; q < 16; q++)
        v[q] = cmul_w(v[q], tw2s[hi * 16 + q]);   // broadcast within half-warp

    __syncthreads();

    // ---- exchange 2: sh[q1*256 + t] ----
#pragma unroll
    for (int q1 = 0; q1 < 16; q1++)
        sh[q1 * 256 + t] = v[q1];
    __syncthreads();
#pragma unroll
    for (int p2 = 0; p2 < 16; p2++)
        v[p2] = sh[hi * 256 + p2 * 16 + k1];

    // ---- pass 3: DFT16 over p2 -> q2;  Y[q2*256 + t] ----
    fft16(v);

    float* outre = out + (size_t)b * NFFT;
    float* outim = out + (size_t)batch * NFFT + (size_t)b * NFFT;
#pragma unroll
    for (int q2 = 0; q2 < 16; q2++) {
        float re, im;
        cunpack(v[q2], re, im);
        __stcs(&outre[q2 * 256 + t], re);
        __stcs(&outim[q2 * 256 + t], im);
    }
}

extern "C" void kernel_launch(void* const* d_in, const int* in_sizes, int n_in,
                              void* d_out, int out_size) {
    const float* xre = (const float*)d_in[0];
    const float* xim = (const float*)d_in[1];
    float* out = (float*)d_out;
    const int batch = in_sizes[0] / NFFT;

    fft4096_kernel<<<batch, TPB>>>(xre, xim, out, batch);
}

// round 12
// speedup vs baseline: 1.2380x; 1.1246x over previous
#include <cuda_runtime.h>
#include <math.h>

// Batched FFT: B=8192 rows, N=4096, complex fp32 (separate re/im), out = [Yre; Yim].
//
// Radix-16^3 four-step, packed f32x2 arithmetic (round-8 skeleton: one row/CTA,
// 3 barriers, 4 CTAs/SM). Round 12: twiddle stage rebuilt as BINARY
// DECOMPOSITION — w^k = (w^8)^b3 (w^4)^b2 (w^2)^b1 w^b0 applied in 4 rounds of
// 8 independent packed cmuls; no serial advance chain at all. Base sincos via
// MUFU __sincosf (args in (-0.4, 0], no range reduction needed).
//
//   n = n1*256 + n2, k = k2*16 + k1, n2 = p1*16 + p2, k2 = q2*16 + q1.
// Pass 1 (t=n2):   A[k1] = DFT16_{n1}(x[n1*256+t]) * W4096^{t*k1}
// Exch 1 (pad 257)
// Pass 2 (k1,p2):  C[q1] = DFT16_{p1}(...) * W256^{p2*q1}
// Exch 2 ([q1*256+t])
// Pass 3 (k1,q1):  Y[q2*256 + t] = DFT16_{p2}(...)

#define NFFT 4096
#define TPB  256

typedef unsigned long long c64;   // packed complex: lo 32 = re, hi 32 = im

__device__ __forceinline__ c64 cpack(float re, float im) {
    c64 r;
    asm("mov.b64 %0, {%1, %2};" : "=l"(r) : "f"(re), "f"(im));
    return r;
}
__device__ __forceinline__ void cunpack(c64 v, float& re, float& im) {
    asm("mov.b64 {%0, %1}, %2;" : "=f"(re), "=f"(im) : "l"(v));
}
__device__ __forceinline__ c64 padd(c64 a, c64 b) {
    c64 r;
    asm("add.rn.f32x2 %0, %1, %2;" : "=l"(r) : "l"(a), "l"(b));
    return r;
}
__device__ __forceinline__ c64 pmul(c64 a, c64 b) {
    c64 r;
    asm("mul.rn.f32x2 %0, %1, %2;" : "=l"(r) : "l"(a), "l"(b));
    return r;
}
__device__ __forceinline__ c64 pfma(c64 a, c64 b, c64 c) {
    c64 r;
    asm("fma.rn.f32x2 %0, %1, %2, %3;" : "=l"(r) : "l"(a), "l"(b), "l"(c));
    return r;
}
__device__ __forceinline__ c64 pswap(c64 a) {   // (re,im) -> (im,re)
    c64 r;
    asm("{\n\t.reg .b32 lo, hi;\n\tmov.b64 {lo, hi}, %1;\n\tmov.b64 %0, {hi, lo};\n\t}"
        : "=l"(r) : "l"(a));
    return r;
}

#define K_NEG1 cpack(-1.0f, -1.0f)
#define K_PM   cpack( 1.0f, -1.0f)
#define K_MP   cpack(-1.0f,  1.0f)

__device__ __forceinline__ c64 psub(c64 a, c64 b) { return pfma(b, K_NEG1, a); }
// complex mul by twiddle held split: xx=(c,c), nyy=(-s,s)
__device__ __forceinline__ c64 cmul_t(c64 a, c64 xx, c64 nyy) {
    return pfma(a, xx, pmul(pswap(a), nyy));
}
// multiply by -i
__device__ __forceinline__ c64 cnegi(c64 a) { return pmul(pswap(a), K_PM); }

// forward DFT4 (W4 = -i), packed
__device__ __forceinline__ void dft4(c64 a, c64 b, c64 c, c64 d,
                                     c64& o0, c64& o1, c64& o2, c64& o3) {
    c64 s0 = padd(a, c);
    c64 s1 = psub(a, c);
    c64 s2 = padd(b, d);
    c64 s3 = psub(b, d);
    o0 = padd(s0, s2);
    o2 = psub(s0, s2);
    c64 s3r = pswap(s3);
    o1 = pfma(s3r, K_PM, s1);   // s1 - i*s3
    o3 = pfma(s3r, K_MP, s1);   // s1 + i*s3
}

// 16-point forward DFT, natural in -> natural out (radix-4 x radix-4), packed.
__device__ __forceinline__ void fft16(c64 v[16]) {
    const float C1 = 0.92387953251128675613f;  // cos(pi/8)
    const float S1 = 0.38268343236508977173f;  // sin(pi/8)
    const float R  = 0.70710678118654752440f;  // sqrt(2)/2

    c64 a[4][4];
#pragma unroll
    for (int l = 0; l < 4; l++)
        dft4(v[l], v[l + 4], v[l + 8], v[l + 12],
             a[l][0], a[l][1], a[l][2], a[l][3]);

    a[1][1] = cmul_t(a[1][1], cpack( C1,  C1), cpack( S1, -S1));
    a[1][2] = cmul_t(a[1][2], cpack(  R,   R), cpack(  R,  -R));
    a[1][3] = cmul_t(a[1][3], cpack( S1,  S1), cpack( C1, -C1));
    a[2][1] = cmul_t(a[2][1], cpack(  R,   R), cpack(  R,  -R));
    a[2][2] = cnegi(a[2][2]);
    a[2][3] = cmul_t(a[2][3], cpack( -R,  -R), cpack(  R,  -R));
    a[3][1] = cmul_t(a[3][1], cpack( S1,  S1), cpack( C1, -C1));
    a[3][2] = cmul_t(a[3][2], cpack( -R,  -R), cpack(  R,  -R));
    a[3][3] = cmul_t(a[3][3], cpack(-C1, -C1), cpack(-S1,  S1));

#pragma unroll
    for (int p = 0; p < 4; p++)
        dft4(a[0][p], a[1][p], a[2][p], a[3][p],
             v[p], v[4 + p], v[8 + p], v[12 + p]);
}

// v[k] *= w^k, k=1..15, via binary decomposition:
//   w^k = (w^8)^b3 (w^4)^b2 (w^2)^b1 (w^1)^b0
// 4 rounds x 8 independent applies; squarings scalar; NO serial chain.
__device__ __forceinline__ void twiddle16_bits(c64 v[16], float ang) {
    float s, c;
    __sincosf(ang, &s, &c);                       // MUFU; |ang| < 0.4
    float c2 = fmaf(c,  c,  -s  * s ),  s2 = 2.0f * c  * s;
    float c4 = fmaf(c2, c2, -s2 * s2),  s4 = 2.0f * c2 * s2;
    float c8 = fmaf(c4, c4, -s4 * s4),  s8 = 2.0f * c4 * s4;

    {   // bit 0: w^1 on odd k
        const c64 xx = cpack(c, c), nn = cpack(-s, s);
#pragma unroll
        for (int k = 1; k < 16; k += 2)
            v[k] = cmul_t(v[k], xx, nn);
    }
    {   // bit 1: w^2 on k with bit1 set
        const c64 xx = cpack(c2, c2), nn = cpack(-s2, s2);
#pragma unroll
        for (int k = 2; k < 16; k += 4) {
            v[k]     = cmul_t(v[k],     xx, nn);
            v[k + 1] = cmul_t(v[k + 1], xx, nn);
        }
    }
    {   // bit 2: w^4 on k in {4..7, 12..15}
        const c64 xx = cpack(c4, c4), nn = cpack(-s4, s4);
#pragma unroll
        for (int k = 4; k < 8; k++) {
            v[k]     = cmul_t(v[k],     xx, nn);
            v[k + 8] = cmul_t(v[k + 8], xx, nn);
        }
    }
    {   // bit 3: w^8 on k >= 8
        const c64 xx = cpack(c8, c8), nn = cpack(-s8, s8);
#pragma unroll
        for (int k = 8; k < 16; k++)
            v[k] = cmul_t(v[k], xx, nn);
    }
}

__global__ void __launch_bounds__(TPB, 4)
fft4096_kernel(const float* __restrict__ xre,
               const float* __restrict__ xim,
               float* __restrict__ out,
               int batch) {
    __shared__ c64 sh[16 * 257];  // 32896 B (257-stride pad for exch 1)

    const int b = blockIdx.x;
    const int t = threadIdx.x;

    const float* xr = xre + (size_t)b * NFFT;
    const float* xi = xim + (size_t)b * NFFT;

    c64 v[16];
#pragma unroll
    for (int n1 = 0; n1 < 16; n1++)
        v[n1] = cpack(__ldcs(&xr[n1 * 256 + t]), __ldcs(&xi[n1 * 256 + t]));

    // ---- pass 1: DFT16 over n1 (thread t = n2), twiddle W4096^{t*k1} ----
    fft16(v);
    twiddle16_bits(v, (float)t * (-6.2831853071795864769f / 4096.0f));

    // ---- exchange 1: sh[k1*257 + n2] ----
#pragma unroll
    for (int k1 = 0; k1 < 16; k1++)
        sh[k1 * 257 + t] = v[k1];
    __syncthreads();

    {
        const int k1 = t & 15;
        const int p2 = t >> 4;
#pragma unroll
        for (int p1 = 0; p1 < 16; p1++)
            v[p1] = sh[k1 * 257 + p1 * 16 + p2];

        // ---- pass 2: DFT16 over p1 -> q1, twiddle W256^{p2*q1} ----
        fft16(v);
        twiddle16_bits(v, (float)p2 * (-6.2831853071795864769f / 256.0f));
    }
    __syncthreads();

    // ---- exchange 2: sh[q1*256 + t] ----
#pragma unroll
    for (int q1 = 0; q1 < 16; q1++)
        sh[q1 * 256 + t] = v[q1];
    __syncthreads();

    {
        const int k1 = t & 15;
        const int q1 = t >> 4;
#pragma unroll
        for (int p2 = 0; p2 < 16; p2++)
            v[p2] = sh[q1 * 256 + p2 * 16 + k1];
    }

    // ---- pass 3: DFT16 over p2 -> q2;  Y[q2*256 + t] ----
    fft16(v);

    float* outre = out + (size_t)b * NFFT;
    float* outim = out + (size_t)batch * NFFT + (size_t)b * NFFT;
#pragma unroll
    for (int q2 = 0; q2 < 16; q2++) {
        float re, im;
        cunpack(v[q2], re, im);
        __stcs(&outre[q2 * 256 + t], re);
        __stcs(&outim[q2 * 256 + t], im);
    }
}

extern "C" void kernel_launch(void* const* d_in, const int* in_sizes, int n_in,
                              void* d_out, int out_size) {
    const float* xre = (const float*)d_in[0];
    const float* xim = (const float*)d_in[1];
    float* out = (float*)d_out;
    const int batch = in_sizes[0] / NFFT;

    fft4096_kernel<<<batch, TPB>>>(xre, xim, out, batch);
}